// round 16
// baseline (speedup 1.0000x reference)
#include <cuda_runtime.h>
#include <math_constants.h>
#include <cstdint>

// Problem constants (B=8, S=1024, V=32000)
#define BB 8
#define SS 1024
#define VV 32000
#define V4 (VV / 4)          // 8000 float4 per logits row
#define NSPLIT 4             // CTAs per batch row (one cluster)
#define QF4 (V4 / NSPLIT)    // 2000 float4 per quarter
#define NBLK (BB * NSPLIT)   // 32 CTAs total

// Output layout (float32, tuple order):
//   [0 .. B*S)               draft        (8192)
//   [B*S .. B*S+B)           num_newly    (8)
//   [B*S+B .. B*S+2B)        num_acc      (8)
//   [B*S+2B .. +B*V)         last_logits  (256000)
#define OFF_NEWLY   (BB * SS)
#define OFF_ACC     (BB * SS + BB)
#define OFF_LOGITS  (BB * SS + 2 * BB)

__device__ __forceinline__ uint32_t smem_u32(const void* p) {
    uint32_t a;
    asm("{ .reg .u64 t; cvta.to.shared.u64 t, %1; cvt.u32.u64 %0, t; }"
        : "=r"(a) : "l"(p));
    return a;
}

// float -> orderable u32 (monotone: bigger float => bigger u32)
__device__ __forceinline__ unsigned f2ord(float v) {
    unsigned u = __float_as_uint(v);
    return (u & 0x80000000u) ? ~u : (u | 0x80000000u);
}

// Warp argmax via redux: (max ord, min idx among holders of the max).
// Equivalent to first-occurrence argmax.
__device__ __forceinline__ void warp_argmax(unsigned ord, unsigned idx,
                                            unsigned& omax, unsigned& imin) {
    asm("redux.sync.max.u32 %0, %1, 0xffffffff;" : "=r"(omax) : "r"(ord));
    unsigned cand = (ord == omax) ? idx : 0xffffffffu;
    asm("redux.sync.min.u32 %0, %1, 0xffffffff;" : "=r"(imin) : "r"(cand));
}

__global__ __launch_bounds__(1024) __cluster_dims__(NSPLIT, 1, 1)
void eagle_kernel(
    const int*   __restrict__ input_ids,   // [B, S]
    const float* __restrict__ logits,      // [B, S, V]
    const int*   __restrict__ npa,         // [B]
    float*       __restrict__ out)
{
    const int b    = blockIdx.x >> 2;    // batch row (cluster id)
    const int tid  = threadIdx.x;
    const int lane = tid & 31;
    const int warp = tid >> 5;

    uint32_t rank;                        // CTA rank within cluster = quarter
    asm("mov.u32 %0, %%cluster_ctarank;" : "=r"(rank));
    const int q = (int)rank;

    __shared__ unsigned s_ord[32], s_sidx[32];
    __shared__ unsigned long long m_cand[NSPLIT];  // rank0's merge mailbox
    __shared__ unsigned long long s_mbar;          // rank0's rendezvous mbar
    __shared__ int s_i0, s_cont, s_bonus;

    const uint32_t mbar_a = smem_u32(&s_mbar);

    // ---- rank0 inits the rendezvous mbarrier; publish via split cluster
    // barrier whose wait is hidden under the DRAM loads below.
    if (q == 0) {
        if (tid == 0) {
            asm volatile("mbarrier.init.shared.b64 [%0], %1;"
                         :: "r"(mbar_a), "r"(NSPLIT - 1) : "memory");
        }
        __syncthreads();                  // order init before rank0's arrive
    }
    asm volatile("barrier.cluster.arrive.aligned;" ::: "memory");

    const int* ids   = input_ids + b * SS;
    const int  start = npa[b] - 1;

    // rank0 prefetches draft source ids (it alone writes the draft row)
    int myid = 0;
    if (q == 0 && tid < SS - 1) myid = ids[tid + 1];

    // ---- issue this CTA's 32KB quarter load of row `start` ----
    const float4* rowq =
        (const float4*)(logits + ((size_t)b * SS + (size_t)start) * VV) + q * QF4;
    const bool t2 = (tid + 1024) < QF4;          // QF4=2000: threads < 976
    float4 v0 = rowq[tid];
    float4 v1 = t2 ? rowq[tid + 1024] : make_float4(0.f, 0.f, 0.f, 0.f);

    // ---- cluster wait here: ~490cy hides under the loads above ----
    asm volatile("barrier.cluster.wait.aligned;" ::: "memory");

    // ---- speculative store: common case this IS last_logits[b] ----
    float4* dstq = (float4*)(out + OFF_LOGITS) + (size_t)b * V4 + q * QF4;
    dstq[tid] = v0;
    if (t2) dstq[tid + 1024] = v1;

    // ---- per-thread partial argmax (global indices, first-occurrence) ----
    float best = -CUDART_INF_F;
    int   bidx = 0x7fffffff;
    {
        int base = (q * QF4 + tid) * 4;
        if (v0.x > best) { best = v0.x; bidx = base;     }
        if (v0.y > best) { best = v0.y; bidx = base + 1; }
        if (v0.z > best) { best = v0.z; bidx = base + 2; }
        if (v0.w > best) { best = v0.w; bidx = base + 3; }
        if (t2) {
            base = (q * QF4 + tid + 1024) * 4;
            if (v1.x > best) { best = v1.x; bidx = base;     }
            if (v1.y > best) { best = v1.y; bidx = base + 1; }
            if (v1.z > best) { best = v1.z; bidx = base + 2; }
            if (v1.w > best) { best = v1.w; bidx = base + 3; }
        }
    }
    unsigned omax, imin;
    warp_argmax(f2ord(best), (unsigned)bidx, omax, imin);
    if (lane == 0) { s_ord[warp] = omax; s_sidx[warp] = imin; }
    __syncthreads();   // orders CTA's speculative STGs before the release-arrive

    if (q != 0) {
        // ===== PEER: merge, DSMEM deposit + release-arrive, exit =====
        if (warp == 0) {
            warp_argmax(s_ord[lane], s_sidx[lane], omax, imin);
            if (lane == 0) {
                unsigned long long pk =
                    ((unsigned long long)omax << 32) | (unsigned)(~imin);
                uint32_t laddr = smem_u32(&m_cand[q]);
                asm volatile(
                    "{ .reg .b32 ra, rb;\n\t"
                    "  mapa.shared::cluster.u32 ra, %0, 0;\n\t"
                    "  st.shared::cluster.b64 [ra], %2;\n\t"
                    "  mapa.shared::cluster.u32 rb, %1, 0;\n\t"
                    "  mbarrier.arrive.release.cluster.shared::cluster.b64 _, [rb]; }"
                    :: "r"(laddr), "r"(mbar_a), "l"(pk) : "memory");
            }
        }
        return;
    }

    // ===================== RANK-0 FINISHER =====================
    if (warp == 0) {
        warp_argmax(s_ord[lane], s_sidx[lane], omax, imin);
        if (lane == 0) {
            m_cand[0] = ((unsigned long long)omax << 32) | (unsigned)(~imin);
            // wait for the 3 peer deposits (acquire, cluster scope)
            unsigned done;
            do {
                asm volatile(
                    "{ .reg .pred p;\n\t"
                    "  mbarrier.try_wait.parity.acquire.cluster.shared::cta.b64 p, [%1], 0, 0x989680;\n\t"
                    "  selp.b32 %0, 1, 0, p; }"
                    : "=r"(done) : "r"(mbar_a) : "memory");
            } while (!done);

            unsigned long long pk = m_cand[0];
            #pragma unroll
            for (int j = 1; j < NSPLIT; j++)
                if (m_cand[j] > pk) pk = m_cand[j];
            s_i0 = (int)(~(unsigned)(pk & 0xFFFFFFFFull));
        }
    }
    __syncthreads();

    int i0 = s_i0;
    int k  = start;

    for (;;) {
        if (tid == 0) {
            if (k < SS - 1 && i0 == ids[k + 1]) {      // L1 hit (prefetched)
                s_cont = 1;
            } else {
                s_cont  = 0;
                s_bonus = i0;
                out[OFF_NEWLY + b] = (float)(k - start);   // num_newly
                out[OFF_ACC   + b] = (float)(k + 1);       // num_acc
            }
        }
        __syncthreads();
        if (!s_cont) break;
        ++k;

        // ---- RARE path: full-row argmax of row k by this CTA alone ----
        const float4* row =
            (const float4*)(logits + ((size_t)b * SS + (size_t)k) * VV);
        float bb2 = -CUDART_INF_F;
        int   bi2 = 0x7fffffff;
        for (int i2 = tid; i2 < V4; i2 += 1024) {
            float4 w = row[i2];
            int base = i2 * 4;
            if (w.x > bb2) { bb2 = w.x; bi2 = base;     }
            if (w.y > bb2) { bb2 = w.y; bi2 = base + 1; }
            if (w.z > bb2) { bb2 = w.z; bi2 = base + 2; }
            if (w.w > bb2) { bb2 = w.w; bi2 = base + 3; }
        }
        unsigned o2, i2m;
        warp_argmax(f2ord(bb2), (unsigned)bi2, o2, i2m);
        if (lane == 0) { s_ord[warp] = o2; s_sidx[warp] = i2m; }
        __syncthreads();
        if (warp == 0) {
            warp_argmax(s_ord[lane], s_sidx[lane], o2, i2m);
            if (lane == 0) s_i0 = (int)i2m;
        }
        __syncthreads();
        i0 = s_i0;
    }

    // ---- draft row (one element per thread; S == blockDim) ----
    int dv;
    if (tid < k)        dv = myid;
    else if (tid == k)  dv = s_bonus;
    else                dv = 0;
    out[b * SS + tid] = (float)dv;

    // ---- RARE correction: overwrite speculative last_logits with row k ----
    // Peers' STGs: syncthreads -> release-arrive -> rank0 acquire try_wait
    // establishes happens-before; safe to overwrite here.
    if (k != start) {
        const float4* row =
            (const float4*)(logits + ((size_t)b * SS + (size_t)k) * VV);
        float4* d2 = (float4*)(out + OFF_LOGITS) + (size_t)b * V4;
        for (int i2 = tid; i2 < V4; i2 += 1024) d2[i2] = row[i2];
    }
}

extern "C" void kernel_launch(void* const* d_in, const int* in_sizes, int n_in,
                              void* d_out, int out_size) {
    const int*   input_ids = (const int*)  d_in[0];
    const float* logits    = (const float*)d_in[1];
    const int*   npa       = (const int*)  d_in[2];
    float* out = (float*)d_out;

    eagle_kernel<<<NBLK, 1024>>>(input_ids, logits, npa, out);
}

// round 17
// speedup vs baseline: 1.3413x; 1.3413x over previous
#include <cuda_runtime.h>
#include <math_constants.h>
#include <cstdint>

// Problem constants (B=8, S=1024, V=32000)
#define BB 8
#define SS 1024
#define VV 32000
#define V4 (VV / 4)          // 8000 float4 per logits row
#define NSPLIT 4             // CTAs per batch row (one cluster)
#define QF4 (V4 / NSPLIT)    // 2000 float4 per quarter
#define NBLK (BB * NSPLIT)   // 32 CTAs total

// Output layout (float32, tuple order):
//   [0 .. B*S)               draft        (8192)
//   [B*S .. B*S+B)           num_newly    (8)
//   [B*S+B .. B*S+2B)        num_acc      (8)
//   [B*S+2B .. +B*V)         last_logits  (256000)
#define OFF_NEWLY   (BB * SS)
#define OFF_ACC     (BB * SS + BB)
#define OFF_LOGITS  (BB * SS + 2 * BB)

__device__ __forceinline__ uint32_t smem_u32(const void* p) {
    uint32_t a;
    asm("{ .reg .u64 t; cvta.to.shared.u64 t, %1; cvt.u32.u64 %0, t; }"
        : "=r"(a) : "l"(p));
    return a;
}

// float -> orderable u32 (monotone: bigger float => bigger u32)
__device__ __forceinline__ unsigned f2ord(float v) {
    unsigned u = __float_as_uint(v);
    return (u & 0x80000000u) ? ~u : (u | 0x80000000u);
}

// Warp argmax via redux: (max ord, min idx among holders of the max).
// Equivalent to first-occurrence argmax.
__device__ __forceinline__ void warp_argmax(unsigned ord, unsigned idx,
                                            unsigned& omax, unsigned& imin) {
    asm("redux.sync.max.u32 %0, %1, 0xffffffff;" : "=r"(omax) : "r"(ord));
    unsigned cand = (ord == omax) ? idx : 0xffffffffu;
    asm("redux.sync.min.u32 %0, %1, 0xffffffff;" : "=r"(imin) : "r"(cand));
}

__global__ __launch_bounds__(1024) __cluster_dims__(NSPLIT, 1, 1)
void eagle_kernel(
    const int*   __restrict__ input_ids,   // [B, S]
    const float* __restrict__ logits,      // [B, S, V]
    const int*   __restrict__ npa,         // [B]
    float*       __restrict__ out)
{
    const int b    = blockIdx.x >> 2;    // batch row (cluster id)
    const int tid  = threadIdx.x;
    const int lane = tid & 31;
    const int warp = tid >> 5;

    uint32_t rank;                        // CTA rank within cluster = quarter
    asm("mov.u32 %0, %%cluster_ctarank;" : "=r"(rank));
    const int q = (int)rank;

    __shared__ unsigned s_ord[32], s_sidx[32];
    __shared__ unsigned long long m_cand[NSPLIT];  // rank0's merge mailbox
    __shared__ int s_i0, s_cont, s_bonus;

    const int* ids   = input_ids + b * SS;
    const int  start = npa[b] - 1;

    // rank0 prefetches draft source ids (it alone writes the draft row)
    int myid = 0;
    if (q == 0 && tid < SS - 1) myid = ids[tid + 1];

    // ---- load this CTA's 32KB quarter of row `start` ----
    const float4* rowq =
        (const float4*)(logits + ((size_t)b * SS + (size_t)start) * VV) + q * QF4;
    const bool t2 = (tid + 1024) < QF4;          // QF4=2000: threads < 976
    float4 v0 = rowq[tid];
    float4 v1 = t2 ? rowq[tid + 1024] : make_float4(0.f, 0.f, 0.f, 0.f);

    // ---- speculative store: common case this IS last_logits[b] ----
    float4* dstq = (float4*)(out + OFF_LOGITS) + (size_t)b * V4 + q * QF4;
    dstq[tid] = v0;
    if (t2) dstq[tid + 1024] = v1;

    // ---- per-thread partial argmax (global indices, first-occurrence) ----
    float best = -CUDART_INF_F;
    int   bidx = 0x7fffffff;
    {
        int base = (q * QF4 + tid) * 4;
        if (v0.x > best) { best = v0.x; bidx = base;     }
        if (v0.y > best) { best = v0.y; bidx = base + 1; }
        if (v0.z > best) { best = v0.z; bidx = base + 2; }
        if (v0.w > best) { best = v0.w; bidx = base + 3; }
        if (t2) {
            base = (q * QF4 + tid + 1024) * 4;
            if (v1.x > best) { best = v1.x; bidx = base;     }
            if (v1.y > best) { best = v1.y; bidx = base + 1; }
            if (v1.z > best) { best = v1.z; bidx = base + 2; }
            if (v1.w > best) { best = v1.w; bidx = base + 3; }
        }
    }
    unsigned omax, imin;
    warp_argmax(f2ord(best), (unsigned)bidx, omax, imin);
    if (lane == 0) { s_ord[warp] = omax; s_sidx[warp] = imin; }
    __syncthreads();

    if (warp == 0) {
        warp_argmax(s_ord[lane], s_sidx[lane], omax, imin);
        if (lane == 0) {
            // pack: max over (ord, then min index on ties)
            unsigned long long pk =
                ((unsigned long long)omax << 32) | (unsigned)(~imin);
            // Deposit candidate into rank 0's mailbox slot [q] via DSMEM.
            uint32_t laddr = smem_u32(&m_cand[q]);
            asm volatile(
                "{ .reg .b32 r;\n\t"
                "  mapa.shared::cluster.u32 r, %0, %1;\n\t"
                "  st.shared::cluster.b64 [r], %2; }"
                :: "r"(laddr), "r"(0), "l"(pk) : "memory");
        }
    }

    // Cluster barrier (acq_rel): publishes mailbox writes AND orders all
    // speculative global stores before rank0's post-barrier work.
    asm volatile("barrier.cluster.arrive.aligned;" ::: "memory");
    asm volatile("barrier.cluster.wait.aligned;"   ::: "memory");

    if (q != 0) return;   // non-leader CTAs are done

    // ===================== RANK-0 FINISHER =====================
    // Lane-parallel merge of the 4 candidates (replaces tid0's serial
    // LDS+compare chain): lanes 0..3 each read one slot, shfl-max merge.
    if (warp == 0) {
        unsigned long long pk = m_cand[lane & 3];
        #pragma unroll
        for (int off = 2; off > 0; off >>= 1) {
            unsigned long long o = __shfl_down_sync(0xffffffffu, pk, off);
            if (o > pk) pk = o;
        }
        if (lane == 0) s_i0 = (int)(~(unsigned)(pk & 0xFFFFFFFFull));
    }
    __syncthreads();

    int i0 = s_i0;
    int k  = start;

    for (;;) {
        if (tid == 0) {
            if (k < SS - 1 && i0 == ids[k + 1]) {      // L1 hit (prefetched)
                s_cont = 1;
            } else {
                s_cont  = 0;
                s_bonus = i0;
                out[OFF_NEWLY + b] = (float)(k - start);   // num_newly
                out[OFF_ACC   + b] = (float)(k + 1);       // num_acc
            }
        }
        __syncthreads();
        if (!s_cont) break;
        ++k;

        // ---- RARE path: full-row argmax of row k by this CTA alone ----
        const float4* row =
            (const float4*)(logits + ((size_t)b * SS + (size_t)k) * VV);
        float bb2 = -CUDART_INF_F;
        int   bi2 = 0x7fffffff;
        for (int i2 = tid; i2 < V4; i2 += 1024) {
            float4 w = row[i2];
            int base = i2 * 4;
            if (w.x > bb2) { bb2 = w.x; bi2 = base;     }
            if (w.y > bb2) { bb2 = w.y; bi2 = base + 1; }
            if (w.z > bb2) { bb2 = w.z; bi2 = base + 2; }
            if (w.w > bb2) { bb2 = w.w; bi2 = base + 3; }
        }
        unsigned o2, i2m;
        warp_argmax(f2ord(bb2), (unsigned)bi2, o2, i2m);
        if (lane == 0) { s_ord[warp] = o2; s_sidx[warp] = i2m; }
        __syncthreads();
        if (warp == 0) {
            warp_argmax(s_ord[lane], s_sidx[lane], o2, i2m);
            if (lane == 0) s_i0 = (int)i2m;
        }
        __syncthreads();
        i0 = s_i0;
    }

    // ---- draft row (one element per thread; S == blockDim) ----
    int dv;
    if (tid < k)        dv = myid;
    else if (tid == k)  dv = s_bonus;
    else                dv = 0;
    out[b * SS + tid] = (float)dv;

    // ---- RARE correction: overwrite speculative last_logits with row k ----
    // Ordering vs. all CTAs' speculative stores was established by the
    // cluster barrier above.
    if (k != start) {
        const float4* row =
            (const float4*)(logits + ((size_t)b * SS + (size_t)k) * VV);
        float4* d2 = (float4*)(out + OFF_LOGITS) + (size_t)b * V4;
        for (int i2 = tid; i2 < V4; i2 += 1024) d2[i2] = row[i2];
    }
}

extern "C" void kernel_launch(void* const* d_in, const int* in_sizes, int n_in,
                              void* d_out, int out_size) {
    const int*   input_ids = (const int*)  d_in[0];
    const float* logits    = (const float*)d_in[1];
    const int*   npa       = (const int*)  d_in[2];
    float* out = (float*)d_out;

    eagle_kernel<<<NBLK, 1024>>>(input_ids, logits, npa, out);
}